// round 16
// baseline (speedup 1.0000x reference)
#include <cuda_runtime.h>
#include <cuda_fp16.h>
#include <cstdint>

// Problem shape (fixed by the dataset)
constexpr int Bsz = 4;
constexpr int Tsz = 2048;
constexpr int Hsz = 2048;
constexpr int BT  = Bsz * Tsz;                 // 8192 GEMM rows
constexpr long TOT = (long)BT * Hsz;           // 16,777,216 elements
constexpr int BH   = Bsz * Hsz;                // 8192 channels
constexpr int NSEG = 32;
constexpr int SEGL = Tsz / NSEG;               // 64 steps per segment
constexpr int BH4  = BH / 4;                   // 2048 4-channel groups
constexpr int H4   = Hsz / 4;                  // 512

// ---------------- scratch (device globals; no cudaMalloc allowed) ----------
__device__ __half g_kx[BT * Hsz];
__device__ __half g_vx[BT * Hsz];
__device__ __half g_rx[BT * Hsz];
__device__ float  g_k [BT * Hsz];
__device__ float  g_v [BT * Hsz];
__device__ float  g_r [BT * Hsz];
__device__ __half g_rc[BT * Hsz];
// transposed fp16 weights: Wt[n][k] = W[k][n]
__device__ __half g_wk[Hsz * Hsz];
__device__ __half g_wv[Hsz * Hsz];
__device__ __half g_wr[Hsz * Hsz];
__device__ __half g_wo[Hsz * Hsz];
// segmented-scan intermediates
__device__ float g_segA[NSEG * BH], g_segB[NSEG * BH], g_segP[NSEG * BH];
__device__ float g_inA [NSEG * BH], g_inB [NSEG * BH], g_inP [NSEG * BH];

// ---------------- PTX helpers ----------------------------------------------
__device__ __forceinline__ uint32_t smem_u32(const void* p) {
    uint32_t a;
    asm("{ .reg .u64 t; cvta.to.shared.u64 t, %1; cvt.u32.u64 %0, t; }" : "=r"(a) : "l"(p));
    return a;
}
#define SW128(off) ((off) ^ (((off) >> 3) & 0x70))
#define CP_ASYNC16(dst, src) \
    asm volatile("cp.async.cg.shared.global [%0], [%1], 16;" :: "r"(dst), "l"(src))
#define CP_COMMIT() asm volatile("cp.async.commit_group;" ::: "memory")

__device__ __forceinline__ void ldsm_x4(uint32_t& r0, uint32_t& r1,
                                        uint32_t& r2, uint32_t& r3, uint32_t addr) {
    asm volatile("ldmatrix.sync.aligned.m8n8.x4.shared.b16 {%0,%1,%2,%3}, [%4];"
                 : "=r"(r0), "=r"(r1), "=r"(r2), "=r"(r3) : "r"(addr));
}
__device__ __forceinline__ void mma16816(float* d, const uint32_t* a, const uint32_t* b) {
    asm volatile(
        "mma.sync.aligned.m16n8k16.row.col.f32.f16.f16.f32 "
        "{%0,%1,%2,%3}, {%4,%5,%6,%7}, {%8,%9}, {%0,%1,%2,%3};"
        : "+f"(d[0]), "+f"(d[1]), "+f"(d[2]), "+f"(d[3])
        : "r"(a[0]), "r"(a[1]), "r"(a[2]), "r"(a[3]), "r"(b[0]), "r"(b[1]));
}

// ---------------- 1) fused prep: token-shift mixes + weight transposes ------
constexpr int MIXB = (int)(TOT / 4 / 256);     // 16384
constexpr int WSB_PER_W = (Hsz / 32) * (Hsz / 64);   // 2048

__global__ void prep_kernel(const float4* __restrict__ hid,
                            const float4* __restrict__ sx,
                            const float4* __restrict__ tmk4,
                            const float4* __restrict__ tmv4,
                            const float4* __restrict__ tmr4,
                            const float* __restrict__ W0,
                            const float* __restrict__ W1,
                            const float* __restrict__ W2,
                            const float* __restrict__ W3)
{
    if (blockIdx.x < MIXB) {
        int i = blockIdx.x * 256 + threadIdx.x;        // float4 index
        long e = (long)i * 4;
        int h4 = (int)(e % Hsz) >> 2;
        int bt = (int)(e / Hsz);
        int t  = bt % Tsz;
        int b  = bt / Tsz;

        float4 cur  = hid[i];
        float4 prev = (t == 0) ? sx[(b * Hsz >> 2) + h4] : hid[i - (Hsz >> 2)];
        float4 mk = tmk4[h4], mv = tmv4[h4], mr = tmr4[h4];

#define MIXOUT(dst, m) { \
        float4 o; \
        o.x = fmaf(cur.x - prev.x, m.x, prev.x); \
        o.y = fmaf(cur.y - prev.y, m.y, prev.y); \
        o.z = fmaf(cur.z - prev.z, m.z, prev.z); \
        o.w = fmaf(cur.w - prev.w, m.w, prev.w); \
        __half2 p0 = __floats2half2_rn(o.x, o.y); \
        __half2 p1 = __floats2half2_rn(o.z, o.w); \
        *reinterpret_cast<__half2*>(dst + e)     = p0; \
        *reinterpret_cast<__half2*>(dst + e + 2) = p1; }
        MIXOUT(g_kx, mk);
        MIXOUT(g_vx, mv);
        MIXOUT(g_rx, mr);
#undef MIXOUT
        return;
    }

    // ---- weight transpose + fp16 convert ----
    __shared__ float tile[64][33];
    int wp  = blockIdx.x - MIXB;
    int z   = wp / WSB_PER_W;
    int rem = wp % WSB_PER_W;
    int bxx = rem & 63;
    int byy = rem >> 6;

    const float* W;
    __half* Tt;
    switch (z) {
        case 0:  W = W0; Tt = g_wk; break;
        case 1:  W = W1; Tt = g_wv; break;
        case 2:  W = W2; Tt = g_wr; break;
        default: W = W3; Tt = g_wo; break;
    }
    const int tx = threadIdx.x & 31, ty = threadIdx.x >> 5;
    const int n0 = bxx * 32;
    const int k0 = byy * 64;
#pragma unroll
    for (int j = 0; j < 64; j += 8)
        tile[ty + j][tx] = W[(long)(k0 + ty + j) * Hsz + n0 + tx];
    __syncthreads();
#pragma unroll
    for (int j = 0; j < 32; j += 8) {
        int n = j + ty;
        __half2 hv = __floats2half2_rn(tile[2 * tx][n], tile[2 * tx + 1][n]);
        *reinterpret_cast<__half2*>(Tt + (long)(n0 + n) * Hsz + k0 + 2 * tx) = hv;
    }
}

// ---------------- 2) HMMA fp16 GEMM (R10 structure, FROZEN) -----------------
constexpr int GBM = 128, GBN = 128, GBK = 64;
constexpr int NKC = Hsz / GBK;                 // 32 chunks
constexpr int TILEB = GBM * 128;               // 16 KB per matrix tile (128B rows)
constexpr int STAGEB = 2 * TILEB;              // 32 KB per stage (A+B)
constexpr int NSTAGE = 3;
constexpr int DSMEM = NSTAGE * STAGEB;         // 96 KB

__device__ __forceinline__ void load_chunk(uint32_t stage,
                                           const __half* A, const __half* Bt,
                                           int brow, int bcol, int kc, int tid)
{
    const int k0 = kc * GBK;
    const uint32_t sA = stage, sB = stage + TILEB;
#pragma unroll
    for (int j = 0; j < 4; j++) {              // 1024 16B chunks per matrix
        int cid = tid + j * 256;
        int r = cid >> 3, c = cid & 7;
        uint32_t so = SW128((uint32_t)(r * 128 + c * 16));
        CP_ASYNC16(sA + so, A  + (long)(brow + r) * Hsz + k0 + c * 8);
        CP_ASYNC16(sB + so, Bt + (long)(bcol + r) * Hsz + k0 + c * 8);
    }
}

template <int NOP>
__global__ __launch_bounds__(256, 2)
void hgemm_kernel(const __half* __restrict__ A0, const __half* __restrict__ B0, float* __restrict__ C0,
                  const __half* __restrict__ A1, const __half* __restrict__ B1, float* __restrict__ C1,
                  const __half* __restrict__ A2, const __half* __restrict__ B2, float* __restrict__ C2)
{
    extern __shared__ char dsm[];
    const uint32_t sbase = smem_u32(dsm);

    const __half* A; const __half* Bt; float* C;
    if (NOP == 1 || blockIdx.z == 0) { A = A0; Bt = B0; C = C0; }
    else if (blockIdx.z == 1)        { A = A1; Bt = B1; C = C1; }
    else                             { A = A2; Bt = B2; C = C2; }

    const int tid = threadIdx.x;
    const int wid = tid >> 5;
    const int lane = tid & 31;
    const int brow = blockIdx.y * GBM;
    const int bcol = blockIdx.x * GBN;

    const int warp_m = (wid & 1) * 64;         // 2 warps along M
    const int warp_n = (wid >> 1) * 32;        // 4 warps along N

    float acc[4][4][4] = {};                   // [mt][nt][frag]
    uint32_t a[2][4][4], b[2][2][4];           // ks-double-buffered fragments

    const int a_row = warp_m + (lane & 15);                       // + mt*16
    const int a_kb  = (lane >> 4) << 4;                           // + ks*32
    const int b_row = warp_n + ((lane >> 4) << 3) + (lane & 7);   // + bp*16
    const int b_kb  = ((lane >> 3) & 1) << 4;                     // + ks*32

    load_chunk(sbase, A, Bt, brow, bcol, 0, tid);
    CP_COMMIT();
    load_chunk(sbase + STAGEB, A, Bt, brow, bcol, 1, tid);
    CP_COMMIT();

    uint32_t stage_off[NSTAGE] = { sbase, sbase + STAGEB, sbase + 2u * STAGEB };

    for (int kc = 0; kc < NKC; kc++) {
        if (kc + 1 < NKC)
            asm volatile("cp.async.wait_group 1;" ::: "memory");
        else
            asm volatile("cp.async.wait_group 0;" ::: "memory");
        __syncthreads();   // chunk kc ready; all warps done reading stage (kc+2)%3

        if (kc + 2 < NKC) {
            load_chunk(stage_off[(kc + 2) % NSTAGE], A, Bt, brow, bcol, kc + 2, tid);
            CP_COMMIT();
        }

        const uint32_t sA = stage_off[kc % NSTAGE];
        const uint32_t sB = sA + TILEB;

        auto fetch = [&](int buf, int ks) {
#pragma unroll
            for (int mt = 0; mt < 4; mt++) {
                uint32_t byte = (uint32_t)((a_row + mt * 16) * 128 + ks * 32 + a_kb);
                ldsm_x4(a[buf][mt][0], a[buf][mt][1], a[buf][mt][2], a[buf][mt][3],
                        sA + SW128(byte));
            }
#pragma unroll
            for (int bp = 0; bp < 2; bp++) {
                uint32_t byte = (uint32_t)((b_row + bp * 16) * 128 + ks * 32 + b_kb);
                ldsm_x4(b[buf][bp][0], b[buf][bp][1], b[buf][bp][2], b[buf][bp][3],
                        sB + SW128(byte));
            }
        };

        fetch(0, 0);
#pragma unroll
        for (int ks = 0; ks < 4; ks++) {
            const int cur = ks & 1;
            if (ks < 3) fetch(cur ^ 1, ks + 1);   // prefetch next ks during MMAs
#pragma unroll
            for (int mt = 0; mt < 4; mt++)
#pragma unroll
                for (int nt = 0; nt < 4; nt++)
                    mma16816(acc[mt][nt], a[cur][mt], &b[cur][nt >> 1][(nt & 1) * 2]);
        }
    }

    // epilogue: direct fp32 stores
#pragma unroll
    for (int mt = 0; mt < 4; mt++) {
        int row0 = brow + warp_m + mt * 16 + (lane >> 2);
#pragma unroll
        for (int nt = 0; nt < 4; nt++) {
            int col = bcol + warp_n + nt * 8 + (lane & 3) * 2;
            float2 lo = make_float2(acc[mt][nt][0], acc[mt][nt][1]);
            float2 hi = make_float2(acc[mt][nt][2], acc[mt][nt][3]);
            *reinterpret_cast<float2*>(C + (long)row0 * Hsz + col)       = lo;
            *reinterpret_cast<float2*>(C + (long)(row0 + 8) * Hsz + col) = hi;
        }
    }
}

// ---------------- 3) WKV segmented scan (4 channels per thread) --------------
__global__ void scan_pass1(const float* __restrict__ tdecay)
{
    int gid = blockIdx.x * blockDim.x + threadIdx.x;
    if (gid >= NSEG * BH4) return;
    const int bh4 = gid & (BH4 - 1);           // BH4 = 2^11
    const int seg = gid >> 11;
    const int b = bh4 >> 9;                    // H4 = 2^9
    const int h = (bh4 & (H4 - 1)) * 4;

    float4 td4 = *reinterpret_cast<const float4*>(tdecay + h);
    float4 w4 = make_float4(-__expf(td4.x), -__expf(td4.y),
                            -__expf(td4.z), -__expf(td4.w));

    const long base = (long)b * Tsz * Hsz + h + (long)seg * SEGL * Hsz;
    const float4* kp = reinterpret_cast<const float4*>(g_k + base);
    const float4* vp = reinterpret_cast<const float4*>(g_v + base);

    float4 a = make_float4(0.f, 0.f, 0.f, 0.f);
    float4 bb = make_float4(0.f, 0.f, 0.f, 0.f);
    float4 p = make_float4(-1e30f, -1e30f, -1e30f, -1e30f);
#pragma unroll 4
    for (int t = 0; t < SEGL; t++) {
        float4 kk = kp[t * H4];
        float4 vv = vp[t * H4];
#define STEP1(c) { \
        float ww2 = w4.c + p.c; \
        float q2  = fmaxf(ww2, kk.c); \
        float f1  = __expf(ww2 - q2); \
        float f2  = __expf(kk.c - q2); \
        a.c  = f1 * a.c  + f2 * vv.c; \
        bb.c = f1 * bb.c + f2; \
        p.c  = q2; }
        STEP1(x) STEP1(y) STEP1(z) STEP1(w)
#undef STEP1
    }
    int sidx = seg * BH4 + bh4;                // float4 slot
    reinterpret_cast<float4*>(g_segA)[sidx] = a;
    reinterpret_cast<float4*>(g_segB)[sidx] = bb;
    reinterpret_cast<float4*>(g_segP)[sidx] = p;
}

// Combine: scalar per channel (hoisted loads), 64-thread blocks for SM spread.
__global__ void scan_combine(const float* __restrict__ hidden,
                             const float* __restrict__ aa0,
                             const float* __restrict__ bb0,
                             const float* __restrict__ pp0,
                             const float* __restrict__ tdecay,
                             float* __restrict__ dout)
{
    int gid = blockIdx.x * blockDim.x + threadIdx.x;
    if (gid >= BH) return;
    const int b = gid >> 11;
    const int h = gid & (Hsz - 1);
    const float w  = -__expf(tdecay[h]);
    const float dL = w * (float)SEGL;

    float As[NSEG], Bs[NSEG], Ps[NSEG];
#pragma unroll
    for (int seg = 0; seg < NSEG; seg++) {     // 96 independent loads
        int idx = seg * BH + gid;
        As[seg] = g_segA[idx];
        Bs[seg] = g_segB[idx];
        Ps[seg] = g_segP[idx];
    }

    float a = aa0[gid], bb = bb0[gid], p = pp0[gid];
#pragma unroll
    for (int seg = 0; seg < NSEG; seg++) {
        int idx = seg * BH + gid;
        g_inA[idx] = a; g_inB[idx] = bb; g_inP[idx] = p;
        float pw = p + dL;
        float po = fmaxf(pw, Ps[seg]);
        float e1 = __expf(pw - po);
        float e2 = __expf(Ps[seg] - po);
        a  = e1 * a  + e2 * As[seg];
        bb = e1 * bb + e2 * Bs[seg];
        p  = po;
    }
    float* st = dout + TOT;
    st[gid]            = hidden[(long)b * Tsz * Hsz + (long)(Tsz - 1) * Hsz + h];
    st[BH + gid]       = a;
    st[2 * BH + gid]   = bb;
    st[3 * BH + gid]   = p;
}

__global__ void scan_pass2(const float* __restrict__ tdecay,
                           const float* __restrict__ tfirst)
{
    int gid = blockIdx.x * blockDim.x + threadIdx.x;
    if (gid >= NSEG * BH4) return;
    const int bh4 = gid & (BH4 - 1);
    const int seg = gid >> 11;
    const int b = bh4 >> 9;
    const int h = (bh4 & (H4 - 1)) * 4;

    float4 u4 = *reinterpret_cast<const float4*>(tfirst + h);
    float4 td4 = *reinterpret_cast<const float4*>(tdecay + h);
    float4 w4 = make_float4(-__expf(td4.x), -__expf(td4.y),
                            -__expf(td4.z), -__expf(td4.w));

    const long base = (long)b * Tsz * Hsz + h + (long)seg * SEGL * Hsz;
    const float4* kp = reinterpret_cast<const float4*>(g_k + base);
    const float4* vp = reinterpret_cast<const float4*>(g_v + base);
    const float4* rp = reinterpret_cast<const float4*>(g_r + base);
    __half* cp = g_rc + base;

    int sidx = seg * BH4 + bh4;
    float4 a  = reinterpret_cast<const float4*>(g_inA)[sidx];
    float4 bb = reinterpret_cast<const float4*>(g_inB)[sidx];
    float4 p  = reinterpret_cast<const float4*>(g_inP)[sidx];

#pragma unroll 4
    for (int t = 0; t < SEGL; t++) {
        float4 kk = kp[t * H4];
        float4 vv = vp[t * H4];
        float4 rr = rp[t * H4];
        float o0, o1, o2, o3;
#define STEP2(c, o) { \
        float ww = u4.c + kk.c; \
        float q  = fmaxf(p.c, ww); \
        float e1 = __expf(p.c - q); \
        float e2 = __expf(ww - q); \
        float num = e1 * a.c  + e2 * vv.c; \
        float den = e1 * bb.c + e2; \
        float sp  = 1.0f + __expf(-rr.c); \
        o = __fdividef(num, den * sp); \
        float ww2 = w4.c + p.c; \
        float q2  = fmaxf(ww2, kk.c); \
        float f1  = __expf(ww2 - q2); \
        float f2  = __expf(kk.c - q2); \
        a.c  = f1 * a.c  + f2 * vv.c; \
        bb.c = f1 * bb.c + f2; \
        p.c  = q2; }
        STEP2(x, o0) STEP2(y, o1) STEP2(z, o2) STEP2(w, o3)
#undef STEP2
        __half2 h0 = __floats2half2_rn(o0, o1);
        __half2 h1 = __floats2half2_rn(o2, o3);
        *reinterpret_cast<__half2*>(cp + (long)t * Hsz)     = h0;
        *reinterpret_cast<__half2*>(cp + (long)t * Hsz + 2) = h1;
    }
}

// ---------------- launch ----------------------------------------------------
extern "C" void kernel_launch(void* const* d_in, const int* in_sizes, int n_in,
                              void* d_out, int out_size)
{
    const float* hidden = (const float*)d_in[0];
    const float* sx     = (const float*)d_in[1];
    const float* aa     = (const float*)d_in[2];
    const float* bb     = (const float*)d_in[3];
    const float* pp     = (const float*)d_in[4];
    const float* td     = (const float*)d_in[5];
    const float* tf     = (const float*)d_in[6];
    const float* tmk    = (const float*)d_in[7];
    const float* tmv    = (const float*)d_in[8];
    const float* tmr    = (const float*)d_in[9];
    const float* Wk     = (const float*)d_in[10];
    const float* Wv     = (const float*)d_in[11];
    const float* Wr     = (const float*)d_in[12];
    const float* Wo     = (const float*)d_in[13];
    float* out = (float*)d_out;

    cudaFuncSetAttribute(hgemm_kernel<3>, cudaFuncAttributeMaxDynamicSharedMemorySize, DSMEM);
    cudaFuncSetAttribute(hgemm_kernel<1>, cudaFuncAttributeMaxDynamicSharedMemorySize, DSMEM);

    void *p_kx, *p_vx, *p_rx, *p_k, *p_v, *p_r, *p_rc;
    void *p_wk, *p_wv, *p_wr, *p_wo;
    cudaGetSymbolAddress(&p_kx, g_kx); cudaGetSymbolAddress(&p_vx, g_vx);
    cudaGetSymbolAddress(&p_rx, g_rx);
    cudaGetSymbolAddress(&p_k, g_k); cudaGetSymbolAddress(&p_v, g_v);
    cudaGetSymbolAddress(&p_r, g_r); cudaGetSymbolAddress(&p_rc, g_rc);
    cudaGetSymbolAddress(&p_wk, g_wk); cudaGetSymbolAddress(&p_wv, g_wv);
    cudaGetSymbolAddress(&p_wr, g_wr); cudaGetSymbolAddress(&p_wo, g_wo);

    // (1) fused prep: mixes + weight transposes in a single launch
    prep_kernel<<<MIXB + 4 * WSB_PER_W, 256>>>(
        (const float4*)hidden, (const float4*)sx,
        (const float4*)tmk, (const float4*)tmv, (const float4*)tmr,
        Wk, Wv, Wr, Wo);

    // (2) k/v/r projection GEMMs, one z-fused launch
    {
        dim3 gg(Hsz / GBN, BT / GBM, 3), gb(256);
        hgemm_kernel<3><<<gg, gb, DSMEM>>>(
            (const __half*)p_kx, (const __half*)p_wk, (float*)p_k,
            (const __half*)p_vx, (const __half*)p_wv, (float*)p_v,
            (const __half*)p_rx, (const __half*)p_wr, (float*)p_r);
    }

    // (3,4,5) segmented WKV scan: pass1 -> combine -> pass2 (4-wide channels)
    scan_pass1 <<<(NSEG * BH4) / 256, 256>>>(td);
    scan_combine<<<BH / 64, 64>>>(hidden, aa, bb, pp, td, out);
    scan_pass2 <<<(NSEG * BH4) / 256, 256>>>(td, tf);

    // (6) output projection
    {
        dim3 gg(Hsz / GBN, BT / GBM, 1), gb(256);
        hgemm_kernel<1><<<gg, gb, DSMEM>>>(
            (const __half*)p_rc, (const __half*)p_wo, out,
            nullptr, nullptr, nullptr, nullptr, nullptr, nullptr);
    }
}

// round 17
// speedup vs baseline: 1.0124x; 1.0124x over previous
#include <cuda_runtime.h>
#include <cuda_fp16.h>
#include <cstdint>

// Problem shape (fixed by the dataset)
constexpr int Bsz = 4;
constexpr int Tsz = 2048;
constexpr int Hsz = 2048;
constexpr int BT  = Bsz * Tsz;                 // 8192 GEMM rows
constexpr long TOT = (long)BT * Hsz;           // 16,777,216 elements
constexpr int BH   = Bsz * Hsz;                // 8192 channels
constexpr int NSEG = 32;
constexpr int SEGL = Tsz / NSEG;               // 64 steps per segment

// ---------------- scratch (device globals; no cudaMalloc allowed) ----------
__device__ __half g_kx[BT * Hsz];
__device__ __half g_vx[BT * Hsz];
__device__ __half g_rx[BT * Hsz];
__device__ float  g_k [BT * Hsz];
__device__ float  g_v [BT * Hsz];
__device__ float  g_r [BT * Hsz];
__device__ __half g_rc[BT * Hsz];
// transposed fp16 weights: Wt[n][k] = W[k][n]
__device__ __half g_wk[Hsz * Hsz];
__device__ __half g_wv[Hsz * Hsz];
__device__ __half g_wr[Hsz * Hsz];
__device__ __half g_wo[Hsz * Hsz];
// segmented-scan intermediates
__device__ float g_segA[NSEG * BH], g_segB[NSEG * BH], g_segP[NSEG * BH];
__device__ float g_inA [NSEG * BH], g_inB [NSEG * BH], g_inP [NSEG * BH];

// ---------------- PTX helpers ----------------------------------------------
__device__ __forceinline__ uint32_t smem_u32(const void* p) {
    uint32_t a;
    asm("{ .reg .u64 t; cvta.to.shared.u64 t, %1; cvt.u32.u64 %0, t; }" : "=r"(a) : "l"(p));
    return a;
}
#define SW128(off) ((off) ^ (((off) >> 3) & 0x70))
#define CP_ASYNC16(dst, src) \
    asm volatile("cp.async.cg.shared.global [%0], [%1], 16;" :: "r"(dst), "l"(src))
#define CP_COMMIT() asm volatile("cp.async.commit_group;" ::: "memory")

__device__ __forceinline__ void ldsm_x4(uint32_t& r0, uint32_t& r1,
                                        uint32_t& r2, uint32_t& r3, uint32_t addr) {
    asm volatile("ldmatrix.sync.aligned.m8n8.x4.shared.b16 {%0,%1,%2,%3}, [%4];"
                 : "=r"(r0), "=r"(r1), "=r"(r2), "=r"(r3) : "r"(addr));
}
__device__ __forceinline__ void mma16816(float* d, const uint32_t* a, const uint32_t* b) {
    asm volatile(
        "mma.sync.aligned.m16n8k16.row.col.f32.f16.f16.f32 "
        "{%0,%1,%2,%3}, {%4,%5,%6,%7}, {%8,%9}, {%0,%1,%2,%3};"
        : "+f"(d[0]), "+f"(d[1]), "+f"(d[2]), "+f"(d[3])
        : "r"(a[0]), "r"(a[1]), "r"(a[2]), "r"(a[3]), "r"(b[0]), "r"(b[1]));
}

// ---------------- 1) fused prep: token-shift mixes + weight transposes ------
constexpr int MIXB = (int)(TOT / 4 / 256);     // 16384
constexpr int WSB_PER_W = (Hsz / 32) * (Hsz / 64);   // 2048

__global__ void prep_kernel(const float4* __restrict__ hid,
                            const float4* __restrict__ sx,
                            const float4* __restrict__ tmk4,
                            const float4* __restrict__ tmv4,
                            const float4* __restrict__ tmr4,
                            const float* __restrict__ W0,
                            const float* __restrict__ W1,
                            const float* __restrict__ W2,
                            const float* __restrict__ W3)
{
    if (blockIdx.x < MIXB) {
        int i = blockIdx.x * 256 + threadIdx.x;        // float4 index
        long e = (long)i * 4;
        int h4 = (int)(e % Hsz) >> 2;
        int bt = (int)(e / Hsz);
        int t  = bt % Tsz;
        int b  = bt / Tsz;

        float4 cur  = hid[i];
        float4 prev = (t == 0) ? sx[(b * Hsz >> 2) + h4] : hid[i - (Hsz >> 2)];
        float4 mk = tmk4[h4], mv = tmv4[h4], mr = tmr4[h4];

#define MIXOUT(dst, m) { \
        float4 o; \
        o.x = fmaf(cur.x - prev.x, m.x, prev.x); \
        o.y = fmaf(cur.y - prev.y, m.y, prev.y); \
        o.z = fmaf(cur.z - prev.z, m.z, prev.z); \
        o.w = fmaf(cur.w - prev.w, m.w, prev.w); \
        __half2 p0 = __floats2half2_rn(o.x, o.y); \
        __half2 p1 = __floats2half2_rn(o.z, o.w); \
        *reinterpret_cast<__half2*>(dst + e)     = p0; \
        *reinterpret_cast<__half2*>(dst + e + 2) = p1; }
        MIXOUT(g_kx, mk);
        MIXOUT(g_vx, mv);
        MIXOUT(g_rx, mr);
#undef MIXOUT
        return;
    }

    // ---- weight transpose + fp16 convert ----
    __shared__ float tile[64][33];
    int wp  = blockIdx.x - MIXB;
    int z   = wp / WSB_PER_W;
    int rem = wp % WSB_PER_W;
    int bxx = rem & 63;
    int byy = rem >> 6;

    const float* W;
    __half* Tt;
    switch (z) {
        case 0:  W = W0; Tt = g_wk; break;
        case 1:  W = W1; Tt = g_wv; break;
        case 2:  W = W2; Tt = g_wr; break;
        default: W = W3; Tt = g_wo; break;
    }
    const int tx = threadIdx.x & 31, ty = threadIdx.x >> 5;
    const int n0 = bxx * 32;
    const int k0 = byy * 64;
#pragma unroll
    for (int j = 0; j < 64; j += 8)
        tile[ty + j][tx] = W[(long)(k0 + ty + j) * Hsz + n0 + tx];
    __syncthreads();
#pragma unroll
    for (int j = 0; j < 32; j += 8) {
        int n = j + ty;
        __half2 hv = __floats2half2_rn(tile[2 * tx][n], tile[2 * tx + 1][n]);
        *reinterpret_cast<__half2*>(Tt + (long)(n0 + n) * Hsz + k0 + 2 * tx) = hv;
    }
}

// ---------------- 2) HMMA fp16 GEMM (R10 structure, FROZEN) -----------------
constexpr int GBM = 128, GBN = 128, GBK = 64;
constexpr int NKC = Hsz / GBK;                 // 32 chunks
constexpr int TILEB = GBM * 128;               // 16 KB per matrix tile (128B rows)
constexpr int STAGEB = 2 * TILEB;              // 32 KB per stage (A+B)
constexpr int NSTAGE = 3;
constexpr int DSMEM = NSTAGE * STAGEB;         // 96 KB

__device__ __forceinline__ void load_chunk(uint32_t stage,
                                           const __half* A, const __half* Bt,
                                           int brow, int bcol, int kc, int tid)
{
    const int k0 = kc * GBK;
    const uint32_t sA = stage, sB = stage + TILEB;
#pragma unroll
    for (int j = 0; j < 4; j++) {              // 1024 16B chunks per matrix
        int cid = tid + j * 256;
        int r = cid >> 3, c = cid & 7;
        uint32_t so = SW128((uint32_t)(r * 128 + c * 16));
        CP_ASYNC16(sA + so, A  + (long)(brow + r) * Hsz + k0 + c * 8);
        CP_ASYNC16(sB + so, Bt + (long)(bcol + r) * Hsz + k0 + c * 8);
    }
}

template <int NOP>
__global__ __launch_bounds__(256, 2)
void hgemm_kernel(const __half* __restrict__ A0, const __half* __restrict__ B0, float* __restrict__ C0,
                  const __half* __restrict__ A1, const __half* __restrict__ B1, float* __restrict__ C1,
                  const __half* __restrict__ A2, const __half* __restrict__ B2, float* __restrict__ C2)
{
    extern __shared__ char dsm[];
    const uint32_t sbase = smem_u32(dsm);

    const __half* A; const __half* Bt; float* C;
    if (NOP == 1 || blockIdx.z == 0) { A = A0; Bt = B0; C = C0; }
    else if (blockIdx.z == 1)        { A = A1; Bt = B1; C = C1; }
    else                             { A = A2; Bt = B2; C = C2; }

    const int tid = threadIdx.x;
    const int wid = tid >> 5;
    const int lane = tid & 31;
    const int brow = blockIdx.y * GBM;
    const int bcol = blockIdx.x * GBN;

    const int warp_m = (wid & 1) * 64;         // 2 warps along M
    const int warp_n = (wid >> 1) * 32;        // 4 warps along N

    float acc[4][4][4] = {};                   // [mt][nt][frag]
    uint32_t a[2][4][4], b[2][2][4];           // ks-double-buffered fragments

    const int a_row = warp_m + (lane & 15);                       // + mt*16
    const int a_kb  = (lane >> 4) << 4;                           // + ks*32
    const int b_row = warp_n + ((lane >> 4) << 3) + (lane & 7);   // + bp*16
    const int b_kb  = ((lane >> 3) & 1) << 4;                     // + ks*32

    load_chunk(sbase, A, Bt, brow, bcol, 0, tid);
    CP_COMMIT();
    load_chunk(sbase + STAGEB, A, Bt, brow, bcol, 1, tid);
    CP_COMMIT();

    uint32_t stage_off[NSTAGE] = { sbase, sbase + STAGEB, sbase + 2u * STAGEB };

    for (int kc = 0; kc < NKC; kc++) {
        if (kc + 1 < NKC)
            asm volatile("cp.async.wait_group 1;" ::: "memory");
        else
            asm volatile("cp.async.wait_group 0;" ::: "memory");
        __syncthreads();   // chunk kc ready; all warps done reading stage (kc+2)%3

        if (kc + 2 < NKC) {
            load_chunk(stage_off[(kc + 2) % NSTAGE], A, Bt, brow, bcol, kc + 2, tid);
            CP_COMMIT();
        }

        const uint32_t sA = stage_off[kc % NSTAGE];
        const uint32_t sB = sA + TILEB;

        auto fetch = [&](int buf, int ks) {
#pragma unroll
            for (int mt = 0; mt < 4; mt++) {
                uint32_t byte = (uint32_t)((a_row + mt * 16) * 128 + ks * 32 + a_kb);
                ldsm_x4(a[buf][mt][0], a[buf][mt][1], a[buf][mt][2], a[buf][mt][3],
                        sA + SW128(byte));
            }
#pragma unroll
            for (int bp = 0; bp < 2; bp++) {
                uint32_t byte = (uint32_t)((b_row + bp * 16) * 128 + ks * 32 + b_kb);
                ldsm_x4(b[buf][bp][0], b[buf][bp][1], b[buf][bp][2], b[buf][bp][3],
                        sB + SW128(byte));
            }
        };

        fetch(0, 0);
#pragma unroll
        for (int ks = 0; ks < 4; ks++) {
            const int cur = ks & 1;
            if (ks < 3) fetch(cur ^ 1, ks + 1);   // prefetch next ks during MMAs
#pragma unroll
            for (int mt = 0; mt < 4; mt++)
#pragma unroll
                for (int nt = 0; nt < 4; nt++)
                    mma16816(acc[mt][nt], a[cur][mt], &b[cur][nt >> 1][(nt & 1) * 2]);
        }
    }

    // epilogue: direct fp32 stores
#pragma unroll
    for (int mt = 0; mt < 4; mt++) {
        int row0 = brow + warp_m + mt * 16 + (lane >> 2);
#pragma unroll
        for (int nt = 0; nt < 4; nt++) {
            int col = bcol + warp_n + nt * 8 + (lane & 3) * 2;
            float2 lo = make_float2(acc[mt][nt][0], acc[mt][nt][1]);
            float2 hi = make_float2(acc[mt][nt][2], acc[mt][nt][3]);
            *reinterpret_cast<float2*>(C + (long)row0 * Hsz + col)       = lo;
            *reinterpret_cast<float2*>(C + (long)(row0 + 8) * Hsz + col) = hi;
        }
    }
}

// ---------------- 3) WKV segmented scan (scalar per channel, R15 proven) -----
__global__ void scan_pass1(const float* __restrict__ tdecay)
{
    int gid = blockIdx.x * blockDim.x + threadIdx.x;
    if (gid >= NSEG * BH) return;
    const int bh  = gid & (BH - 1);
    const int seg = gid >> 13;                 // BH = 2^13
    const int b = bh >> 11;                    // Hsz = 2^11
    const int h = bh & (Hsz - 1);

    const float w = -__expf(tdecay[h]);
    const long base = (long)b * Tsz * Hsz + h + (long)seg * SEGL * Hsz;
    const float* kp = g_k + base;
    const float* vp = g_v + base;

    float a = 0.f, bb = 0.f, p = -1e30f;
#pragma unroll 4
    for (int t = 0; t < SEGL; t++) {
        float kk = kp[(long)t * Hsz];
        float vv = vp[(long)t * Hsz];
        float ww2 = w + p;
        float q2  = fmaxf(ww2, kk);
        float f1  = __expf(ww2 - q2);
        float f2  = __expf(kk - q2);
        a  = f1 * a  + f2 * vv;
        bb = f1 * bb + f2;
        p  = q2;
    }
    g_segA[gid] = a; g_segB[gid] = bb; g_segP[gid] = p;
}

// Combine: hoisted loads (R15) + 64-thread blocks for SM spread (R16 win).
__global__ void scan_combine(const float* __restrict__ hidden,
                             const float* __restrict__ aa0,
                             const float* __restrict__ bb0,
                             const float* __restrict__ pp0,
                             const float* __restrict__ tdecay,
                             float* __restrict__ dout)
{
    int gid = blockIdx.x * blockDim.x + threadIdx.x;
    if (gid >= BH) return;
    const int b = gid >> 11;
    const int h = gid & (Hsz - 1);
    const float w  = -__expf(tdecay[h]);
    const float dL = w * (float)SEGL;

    float As[NSEG], Bs[NSEG], Ps[NSEG];
#pragma unroll
    for (int seg = 0; seg < NSEG; seg++) {     // 96 independent loads
        int idx = seg * BH + gid;
        As[seg] = g_segA[idx];
        Bs[seg] = g_segB[idx];
        Ps[seg] = g_segP[idx];
    }

    float a = aa0[gid], bb = bb0[gid], p = pp0[gid];
#pragma unroll
    for (int seg = 0; seg < NSEG; seg++) {
        int idx = seg * BH + gid;
        g_inA[idx] = a; g_inB[idx] = bb; g_inP[idx] = p;
        float pw = p + dL;
        float po = fmaxf(pw, Ps[seg]);
        float e1 = __expf(pw - po);
        float e2 = __expf(Ps[seg] - po);
        a  = e1 * a  + e2 * As[seg];
        bb = e1 * bb + e2 * Bs[seg];
        p  = po;
    }
    float* st = dout + TOT;
    st[gid]            = hidden[(long)b * Tsz * Hsz + (long)(Tsz - 1) * Hsz + h];
    st[BH + gid]       = a;
    st[2 * BH + gid]   = bb;
    st[3 * BH + gid]   = p;
}

__global__ void scan_pass2(const float* __restrict__ tdecay,
                           const float* __restrict__ tfirst)
{
    int gid = blockIdx.x * blockDim.x + threadIdx.x;
    if (gid >= NSEG * BH) return;
    const int bh  = gid & (BH - 1);
    const int seg = gid >> 13;
    const int b = bh >> 11;
    const int h = bh & (Hsz - 1);

    const float u = tfirst[h];
    const float w = -__expf(tdecay[h]);
    const long base = (long)b * Tsz * Hsz + h + (long)seg * SEGL * Hsz;
    const float* kp = g_k + base;
    const float* vp = g_v + base;
    const float* rp = g_r + base;
    __half* cp = g_rc + base;

    float a  = g_inA[gid];
    float bb = g_inB[gid];
    float p  = g_inP[gid];

#pragma unroll 4
    for (int t = 0; t < SEGL; t++) {
        float kk = kp[(long)t * Hsz];
        float vv = vp[(long)t * Hsz];
        float rr = rp[(long)t * Hsz];
        float ww = u + kk;
        float q  = fmaxf(p, ww);
        float e1 = __expf(p - q);
        float e2 = __expf(ww - q);
        float num = e1 * a  + e2 * vv;
        float den = e1 * bb + e2;
        float sp  = 1.0f + __expf(-rr);
        cp[(long)t * Hsz] = __float2half_rn(__fdividef(num, den * sp));
        float ww2 = w + p;
        float q2  = fmaxf(ww2, kk);
        float f1  = __expf(ww2 - q2);
        float f2  = __expf(kk - q2);
        a  = f1 * a  + f2 * vv;
        bb = f1 * bb + f2;
        p  = q2;
    }
}

// ---------------- launch ----------------------------------------------------
extern "C" void kernel_launch(void* const* d_in, const int* in_sizes, int n_in,
                              void* d_out, int out_size)
{
    const float* hidden = (const float*)d_in[0];
    const float* sx     = (const float*)d_in[1];
    const float* aa     = (const float*)d_in[2];
    const float* bb     = (const float*)d_in[3];
    const float* pp     = (const float*)d_in[4];
    const float* td     = (const float*)d_in[5];
    const float* tf     = (const float*)d_in[6];
    const float* tmk    = (const float*)d_in[7];
    const float* tmv    = (const float*)d_in[8];
    const float* tmr    = (const float*)d_in[9];
    const float* Wk     = (const float*)d_in[10];
    const float* Wv     = (const float*)d_in[11];
    const float* Wr     = (const float*)d_in[12];
    const float* Wo     = (const float*)d_in[13];
    float* out = (float*)d_out;

    cudaFuncSetAttribute(hgemm_kernel<3>, cudaFuncAttributeMaxDynamicSharedMemorySize, DSMEM);
    cudaFuncSetAttribute(hgemm_kernel<1>, cudaFuncAttributeMaxDynamicSharedMemorySize, DSMEM);

    void *p_kx, *p_vx, *p_rx, *p_k, *p_v, *p_r, *p_rc;
    void *p_wk, *p_wv, *p_wr, *p_wo;
    cudaGetSymbolAddress(&p_kx, g_kx); cudaGetSymbolAddress(&p_vx, g_vx);
    cudaGetSymbolAddress(&p_rx, g_rx);
    cudaGetSymbolAddress(&p_k, g_k); cudaGetSymbolAddress(&p_v, g_v);
    cudaGetSymbolAddress(&p_r, g_r); cudaGetSymbolAddress(&p_rc, g_rc);
    cudaGetSymbolAddress(&p_wk, g_wk); cudaGetSymbolAddress(&p_wv, g_wv);
    cudaGetSymbolAddress(&p_wr, g_wr); cudaGetSymbolAddress(&p_wo, g_wo);

    // (1) fused prep: mixes + weight transposes in a single launch
    prep_kernel<<<MIXB + 4 * WSB_PER_W, 256>>>(
        (const float4*)hidden, (const float4*)sx,
        (const float4*)tmk, (const float4*)tmv, (const float4*)tmr,
        Wk, Wv, Wr, Wo);

    // (2) k/v/r projection GEMMs, one z-fused launch
    {
        dim3 gg(Hsz / GBN, BT / GBM, 3), gb(256);
        hgemm_kernel<3><<<gg, gb, DSMEM>>>(
            (const __half*)p_kx, (const __half*)p_wk, (float*)p_k,
            (const __half*)p_vx, (const __half*)p_wv, (float*)p_v,
            (const __half*)p_rx, (const __half*)p_wr, (float*)p_r);
    }

    // (3,4,5) segmented WKV scan: pass1 -> combine -> pass2
    scan_pass1 <<<(NSEG * BH) / 256, 256>>>(td);
    scan_combine<<<BH / 64, 64>>>(hidden, aa, bb, pp, td, out);
    scan_pass2 <<<(NSEG * BH) / 256, 256>>>(td, tf);

    // (6) output projection
    {
        dim3 gg(Hsz / GBN, BT / GBM, 1), gb(256);
        hgemm_kernel<1><<<gg, gb, DSMEM>>>(
            (const __half*)p_rc, (const __half*)p_wo, out,
            nullptr, nullptr, nullptr, nullptr, nullptr, nullptr);
    }
}